// round 11
// baseline (speedup 1.0000x reference)
#include <cuda_runtime.h>
#include <cuda_bf16.h>
#include <cstdint>

// ===========================================================================
// MoE AG-scatter grouped GEMM via mma.sync bf16, 2-term fp32 split (3 products)
//   out[s,:] = x[token(s),:] @ W[e(s),:,:]^T
// R11 = R9 pipeline (BK=32, 3-stage cp.async, 1 bar.sync/chunk, XOR swizzle,
//   mid-chunk load placement, 2 CTAs/SM persistent) with CTA tile 64x128
//   (8 warps 2Mx4N, warp tile 32x32). BM=64 makes njobs <= 2112 < 304*7,
//   guaranteeing a 7-round makespan of half-size jobs vs 4 rounds of full
//   jobs (kills the 10.5% last-wave quantization idle).
// ===========================================================================

#define NTOK   8192
#define TOPK   2
#define MTOT   (NTOK * TOPK)          // 16384
#define NDIM   1024
#define KDIM   1024
#define NEXP   8

#define BM     64
#define BN     128
#define BK     32                     // bf16 k per chunk
#define NCHUNK (KDIM / BK)            // 32
#define NSTAGE 3
#define NBLK   (NDIM / BN)            // 8
#define MAXTILES (MTOT / BM + NEXP)   // 264

#define RSTR   64                     // unpadded row stride (bytes)
#define OFF_AH 0
#define OFF_AL 4096
#define OFF_BH 8192
#define OFF_BL 16384
#define STAGE_BYTES 24576             // Ah 4K + Al 4K + Bh 8K + Bl 8K
#define SMEM_TOTAL  (NSTAGE * STAGE_BYTES + 512 + 16)

// ---------------- device-global scratch ------------------------------------
__device__ int g_token_of_row[MTOT];
__device__ int g_tile_e[MAXTILES];
__device__ int g_tile_row0[MAXTILES];
__device__ int g_tile_rows[MAXTILES];
__device__ int g_njobs;
__device__ int g_job;
__device__ __align__(16) __nv_bfloat16 g_A_hi[(size_t)NTOK * KDIM];
__device__ __align__(16) __nv_bfloat16 g_A_lo[(size_t)NTOK * KDIM];
__device__ __align__(16) __nv_bfloat16 g_W_hi[(size_t)NEXP * NDIM * KDIM];
__device__ __align__(16) __nv_bfloat16 g_W_lo[(size_t)NEXP * NDIM * KDIM];

// ---------------- helpers ---------------------------------------------------
__device__ __forceinline__ uint32_t smem_to_u32(const void* p) {
    uint32_t a;
    asm("{ .reg .u64 t; cvta.to.shared.u64 t, %1; cvt.u32.u64 %0, t; }"
        : "=r"(a) : "l"(p));
    return a;
}

#define CPA16(dst_u32, src_ptr) \
    asm volatile("cp.async.cg.shared.global [%0], [%1], 16;" \
        :: "r"(dst_u32), "l"(src_ptr))
#define CPA_COMMIT() asm volatile("cp.async.commit_group;")
#define CPA_WAIT1()  asm volatile("cp.async.wait_group 1;")
#define CPA_WAIT0()  asm volatile("cp.async.wait_group 0;")

__device__ __forceinline__ void ldsm_x4(uint32_t r[4], uint32_t addr) {
    asm volatile("ldmatrix.sync.aligned.m8n8.x4.shared.b16 {%0,%1,%2,%3}, [%4];"
        : "=r"(r[0]), "=r"(r[1]), "=r"(r[2]), "=r"(r[3]) : "r"(addr));
}

__device__ __forceinline__ void mma_bf16(float d[4],
    const uint32_t a[4], uint32_t b0, uint32_t b1)
{
    asm volatile(
        "mma.sync.aligned.m16n8k16.row.col.f32.bf16.bf16.f32 "
        "{%0,%1,%2,%3}, {%4,%5,%6,%7}, {%8,%9}, {%0,%1,%2,%3};"
        : "+f"(d[0]), "+f"(d[1]), "+f"(d[2]), "+f"(d[3])
        : "r"(a[0]), "r"(a[1]), "r"(a[2]), "r"(a[3]), "r"(b0), "r"(b1));
}

__device__ __forceinline__ void split_store(float4 v, __nv_bfloat16* hi,
                                            __nv_bfloat16* lo, size_t o)
{
    __nv_bfloat16 h0 = __float2bfloat16(v.x), h1 = __float2bfloat16(v.y);
    __nv_bfloat16 h2 = __float2bfloat16(v.z), h3 = __float2bfloat16(v.w);
    __nv_bfloat16 l0 = __float2bfloat16(v.x - __bfloat162float(h0));
    __nv_bfloat16 l1 = __float2bfloat16(v.y - __bfloat162float(h1));
    __nv_bfloat16 l2 = __float2bfloat16(v.z - __bfloat162float(h2));
    __nv_bfloat16 l3 = __float2bfloat16(v.w - __bfloat162float(h3));
    *(ushort4*)(hi + o) = make_ushort4(
        __bfloat16_as_ushort(h0), __bfloat16_as_ushort(h1),
        __bfloat16_as_ushort(h2), __bfloat16_as_ushort(h3));
    *(ushort4*)(lo + o) = make_ushort4(
        __bfloat16_as_ushort(l0), __bfloat16_as_ushort(l1),
        __bfloat16_as_ushort(l2), __bfloat16_as_ushort(l3));
}

// ---------------- fused prep (2 float4 per thread, MLP=2) -------------------
#define WBLK 4096
#define ABLK 4096
#define MBLK (MTOT / 256)             // 64
#define PREP_GRID (WBLK + ABLK + MBLK + 1)

__global__ __launch_bounds__(256) void prep_all(
    const float* __restrict__ x, const float* __restrict__ w,
    const int* __restrict__ scatter, const int* __restrict__ splits)
{
    int b = blockIdx.x;
    if (b < WBLK + ABLK) {
        const bool isW = (b < WBLK);
        const float* src = isW ? w : x;
        __nv_bfloat16* hi = isW ? g_W_hi : g_A_hi;
        __nv_bfloat16* lo = isW ? g_W_lo : g_A_lo;
        size_t q = ((size_t)(isW ? b : b - WBLK) * 512 + threadIdx.x);
        size_t o0 = q * 4;
        size_t o1 = (q + 256) * 4;
        float4 v0 = *(const float4*)(src + o0);
        float4 v1 = *(const float4*)(src + o1);
        split_store(v0, hi, lo, o0);
        split_store(v1, hi, lo, o1);
    } else if (b < WBLK + ABLK + MBLK) {
        int f = (b - WBLK - ABLK) * 256 + threadIdx.x;
        g_token_of_row[scatter[f]] = f / TOPK;
    } else if (threadIdx.x == 0) {
        int cum = 0, t = 0;
        for (int e = 0; e < NEXP; e++) {
            int cnt = splits[e];
            for (int r0 = 0; r0 < cnt; r0 += BM) {
                g_tile_e[t] = e;
                g_tile_row0[t] = cum + r0;
                g_tile_rows[t] = (cnt - r0 < BM) ? (cnt - r0) : BM;
                t++;
            }
            cum += cnt;
        }
        g_njobs = t * NBLK;
        g_job = 0;
    }
}

// ---------------- main GEMM --------------------------------------------------
// Stage: Ah/Al 64 rows + Bh/Bl 128 rows, 64B data rows, 1536 x 16B cp.async.
__device__ __forceinline__ void load_stage(uint32_t sbuf, int c, int wbase,
                                           const int* s_tok, int tid)
{
    const size_t kb = (size_t)c * BK;
    #pragma unroll
    for (int i = 0; i < 6; i++) {
        int o = tid + i * 256;            // 0..1535 ; i<2 -> A, i>=2 -> B
        const char* src;
        uint32_t dst;
        if (o < 512) {                    // A hi/lo (64 rows each)
            int t4  = o >> 8;             // 0=Ah,1=Al
            int r   = (o >> 2) & 63;
            int seg = o & 3;
            int sw  = seg ^ ((r >> 1) & 3);
            dst = sbuf + t4 * 4096 + r * RSTR + sw * 16;
            int tok = s_tok[r];
            const __nv_bfloat16* base = (t4 == 0) ? g_A_hi : g_A_lo;
            src = (const char*)(base + (size_t)tok * KDIM + kb) + seg * 16;
        } else {                          // B hi/lo (128 rows each)
            int bo2 = o - 512;
            int t4  = bo2 >> 9;           // 0=Bh,1=Bl
            int r   = (bo2 >> 2) & 127;
            int seg = bo2 & 3;
            int sw  = seg ^ ((r >> 1) & 3);
            dst = sbuf + OFF_BH + t4 * 8192 + r * RSTR + sw * 16;
            const __nv_bfloat16* base = (t4 == 0) ? g_W_hi : g_W_lo;
            src = (const char*)(base + (size_t)(wbase + r) * KDIM + kb) + seg * 16;
        }
        CPA16(dst, src);
    }
}

__global__ __launch_bounds__(256, 2) void moe_gemm_mma(float* __restrict__ out)
{
    extern __shared__ char smem_raw[];
    const uint32_t stage0 = smem_to_u32(smem_raw);
    int* s_tok = (int*)(smem_raw + NSTAGE * STAGE_BYTES);
    int* s_job = (int*)(smem_raw + NSTAGE * STAGE_BYTES + 512);

    const int tid  = threadIdx.x;
    const int wid  = tid >> 5;
    const int lane = tid & 31;
    const int wm   = wid & 1;          // 2 warps along M (32 rows each)
    const int wn   = wid >> 1;         // 4 warps along N (32 cols each)

    // ldmatrix lane rows + per-row swizzle masks
    const int a_r   = (lane & 7) + ((lane >> 3) & 1) * 8;
    const int a_c16 = lane >> 4;
    uint32_t rowA[2]; int mA[2];
    #pragma unroll
    for (int mt = 0; mt < 2; mt++) {
        int r = wm * 32 + mt * 16 + a_r;
        rowA[mt] = r * RSTR;
        mA[mt] = (r >> 1) & 3;
    }
    const int b_r   = (lane & 7) + ((lane >> 4) & 1) * 8;
    const int b_k16 = (lane >> 3) & 1;
    uint32_t rowB[2]; int mB[2];
    #pragma unroll
    for (int np = 0; np < 2; np++) {
        int r = wn * 32 + np * 16 + b_r;
        rowB[np] = r * RSTR;
        mB[np] = (r >> 1) & 3;
    }

    const int njobs = g_njobs;

    while (true) {
        __syncthreads();                          // smem free from previous job
        if (tid == 0) *s_job = atomicAdd(&g_job, 1);
        __syncthreads();
        const int job = *s_job;
        if (job >= njobs) break;

        const int tile = job >> 3;                // NBLK = 8
        const int nb   = job & 7;
        const int nrows = g_tile_rows[tile];
        const int row0  = g_tile_row0[tile];
        const int e     = g_tile_e[tile];
        const int n0    = nb * BN;
        const int wbase = e * NDIM + n0;

        if (tid < 64)
            s_tok[tid] = (tid < nrows) ? g_token_of_row[row0 + tid] : 0;
        __syncthreads();

        float acc[2][4][4];
        #pragma unroll
        for (int mt = 0; mt < 2; mt++)
            #pragma unroll
            for (int nt = 0; nt < 4; nt++)
                #pragma unroll
                for (int q = 0; q < 4; q++)
                    acc[mt][nt][q] = 0.0f;

        // prologue: 2 stages in flight
        load_stage(stage0, 0, wbase, s_tok, tid);
        CPA_COMMIT();
        load_stage(stage0 + STAGE_BYTES, 1, wbase, s_tok, tid);
        CPA_COMMIT();

        uint32_t sbuf = stage0;
        for (int c = 0; c < NCHUNK; c++) {
            if (c < NCHUNK - 1) { CPA_WAIT1(); } else { CPA_WAIT0(); }
            __syncthreads();                      // single barrier per chunk

            // ---- ks = 0 half: ldsm/MMA restart immediately ----
            {
                uint32_t Ah[2][4], Al[2][4];
                #pragma unroll
                for (int mt = 0; mt < 2; mt++) {
                    const uint32_t ao = rowA[mt] +
                        (uint32_t)((a_c16 ^ mA[mt]) << 4);
                    ldsm_x4(Ah[mt], sbuf + OFF_AH + ao);
                    ldsm_x4(Al[mt], sbuf + OFF_AL + ao);
                }
                #pragma unroll
                for (int np = 0; np < 2; np++) {
                    const uint32_t bo = rowB[np] +
                        (uint32_t)((b_k16 ^ mB[np]) << 4);
                    uint32_t Bh[4], Bl[4];
                    ldsm_x4(Bh, sbuf + OFF_BH + bo);
                    ldsm_x4(Bl, sbuf + OFF_BL + bo);
                    #pragma unroll
                    for (int mt = 0; mt < 2; mt++) {
                        float* d0 = acc[mt][2 * np];
                        float* d1 = acc[mt][2 * np + 1];
                        mma_bf16(d0, Ah[mt], Bh[0], Bh[1]);
                        mma_bf16(d1, Ah[mt], Bh[2], Bh[3]);
                        mma_bf16(d0, Ah[mt], Bl[0], Bl[1]);
                        mma_bf16(d1, Ah[mt], Bl[2], Bl[3]);
                        mma_bf16(d0, Al[mt], Bh[0], Bh[1]);
                        mma_bf16(d1, Al[mt], Bh[2], Bh[3]);
                    }
                }
            }

            // ---- issue next stage's loads while ks=0 MMAs drain ----
            if (c + 2 < NCHUNK) {
                uint32_t nbuf = sbuf + 2 * STAGE_BYTES;
                if (nbuf >= stage0 + 3 * STAGE_BYTES) nbuf -= 3 * STAGE_BYTES;
                load_stage(nbuf, c + 2, wbase, s_tok, tid);
                CPA_COMMIT();
            }

            // ---- ks = 1 half ----
            {
                uint32_t Ah[2][4], Al[2][4];
                #pragma unroll
                for (int mt = 0; mt < 2; mt++) {
                    const uint32_t ao = rowA[mt] +
                        (uint32_t)(((a_c16 + 2) ^ mA[mt]) << 4);
                    ldsm_x4(Ah[mt], sbuf + OFF_AH + ao);
                    ldsm_x4(Al[mt], sbuf + OFF_AL + ao);
                }
                #pragma unroll
                for (int np = 0; np < 2; np++) {
                    const uint32_t bo = rowB[np] +
                        (uint32_t)(((b_k16 + 2) ^ mB[np]) << 4);
                    uint32_t Bh[4], Bl[4];
                    ldsm_x4(Bh, sbuf + OFF_BH + bo);
                    ldsm_x4(Bl, sbuf + OFF_BL + bo);
                    #pragma unroll
                    for (int mt = 0; mt < 2; mt++) {
                        float* d0 = acc[mt][2 * np];
                        float* d1 = acc[mt][2 * np + 1];
                        mma_bf16(d0, Ah[mt], Bh[0], Bh[1]);
                        mma_bf16(d1, Ah[mt], Bh[2], Bh[3]);
                        mma_bf16(d0, Ah[mt], Bl[0], Bl[1]);
                        mma_bf16(d1, Ah[mt], Bl[2], Bl[3]);
                        mma_bf16(d0, Al[mt], Bh[0], Bh[1]);
                        mma_bf16(d1, Al[mt], Bh[2], Bh[3]);
                    }
                }
            }

            sbuf += STAGE_BYTES;
            if (sbuf >= stage0 + 3 * STAGE_BYTES) sbuf = stage0;
        }

        // epilogue: warp stores its 32x32 region
        const int g = lane >> 2;
        const int t = lane & 3;
        #pragma unroll
        for (int mt = 0; mt < 2; mt++) {
            const int mBase = wm * 32 + mt * 16;
            const int m0 = mBase + g;
            const int m1 = mBase + g + 8;
            float* r0p = out + (size_t)(row0 + m0) * NDIM + n0 + wn * 32 + 2 * t;
            float* r1p = out + (size_t)(row0 + m1) * NDIM + n0 + wn * 32 + 2 * t;
            #pragma unroll
            for (int nt = 0; nt < 4; nt++) {
                if (m0 < nrows) {
                    float2 v; v.x = acc[mt][nt][0]; v.y = acc[mt][nt][1];
                    *(float2*)(r0p + nt * 8) = v;
                }
                if (m1 < nrows) {
                    float2 v; v.x = acc[mt][nt][2]; v.y = acc[mt][nt][3];
                    *(float2*)(r1p + nt * 8) = v;
                }
            }
        }
    }
}

// ---------------------------------------------------------------------------
extern "C" void kernel_launch(void* const* d_in, const int* in_sizes, int n_in,
                              void* d_out, int out_size) {
    const float* x       = (const float*)d_in[0];
    const float* weights = (const float*)d_in[1];
    const int*   scatter = (const int*)d_in[2];
    const int*   splits  = (const int*)d_in[3];
    float*       out     = (float*)d_out;
    (void)in_sizes; (void)n_in; (void)out_size;

    cudaFuncSetAttribute(moe_gemm_mma,
                         cudaFuncAttributeMaxDynamicSharedMemorySize, SMEM_TOTAL);

    prep_all<<<PREP_GRID, 256>>>(x, weights, scatter, splits);
    moe_gemm_mma<<<304, 256, SMEM_TOTAL>>>(out);   // persistent, 2 CTAs/SM
}

// round 12
// speedup vs baseline: 1.1493x; 1.1493x over previous
#include <cuda_runtime.h>
#include <cuda_bf16.h>
#include <cstdint>

// ===========================================================================
// MoE AG-scatter grouped GEMM via single-pass TF32 mma.sync.
//   out[s,:] = x[token(s),:] @ W[e(s),:,:]^T      (fp32 in/out)
// R12: no data prep at all -- cp.async loads the ORIGINAL fp32 x / W tiles;
//   fragments are rounded in-register with cvt.rna.tf32 (unbiased; raw
//   truncation would give a coherent ~1e-3 bias). One tf32 product replaces
//   the 3 bf16-split products: tensor instructions x0.67, prep 18us -> 2us.
// Pipeline = R9's proven shape: BK=32 (4 tf32 k-steps), 3-stage cp.async,
//   one __syncthreads per chunk, mid-chunk load placement, CTA 128x128,
//   8 warps (4M x 2N, warp tile 32x64), 2 CTAs/SM, persistent job loop.
// SMEM: A 128 rows x 128B, XOR swizzle seg^=(row&7) -> ldmatrix-b16-on-fp32
//   trick delivers exact tf32 A-fragments conflict-free. B 128 rows x 144B
//   stride -> ld.shared.b32 B-fragments conflict-free (bank = 4n+k).
// ===========================================================================

#define NTOK   8192
#define TOPK   2
#define MTOT   (NTOK * TOPK)          // 16384
#define NDIM   1024
#define KDIM   1024
#define NEXP   8

#define BM     128
#define BN     128
#define BK     32                     // fp32 k per chunk = 4 tf32 k-steps
#define NCHUNK (KDIM / BK)            // 32
#define NSTAGE 3
#define NBLK   (NDIM / BN)            // 8
#define MAXTILES (MTOT / BM + NEXP)   // 136

#define ASTRIDE 128                   // A row bytes (8 x 16B segs, swizzled)
#define BSTRIDE 144                   // B row bytes (128B data + 16B pad)
#define OFF_B   (128 * ASTRIDE)       // 16384
#define STAGE_BYTES (OFF_B + 128 * BSTRIDE)        // 34816
#define SMEM_TOTAL  (NSTAGE * STAGE_BYTES + 512 + 16)   // 104976

// ---------------- device-global scratch ------------------------------------
__device__ int g_token_of_row[MTOT];
__device__ int g_tile_e[MAXTILES];
__device__ int g_tile_row0[MAXTILES];
__device__ int g_tile_rows[MAXTILES];
__device__ int g_njobs;
__device__ int g_job;

// ---------------- helpers ---------------------------------------------------
__device__ __forceinline__ uint32_t smem_to_u32(const void* p) {
    uint32_t a;
    asm("{ .reg .u64 t; cvta.to.shared.u64 t, %1; cvt.u32.u64 %0, t; }"
        : "=r"(a) : "l"(p));
    return a;
}

#define CPA16(dst_u32, src_ptr) \
    asm volatile("cp.async.cg.shared.global [%0], [%1], 16;" \
        :: "r"(dst_u32), "l"(src_ptr))
#define CPA_COMMIT() asm volatile("cp.async.commit_group;")
#define CPA_WAIT1()  asm volatile("cp.async.wait_group 1;")
#define CPA_WAIT0()  asm volatile("cp.async.wait_group 0;")

__device__ __forceinline__ void ldsm_x4(uint32_t r[4], uint32_t addr) {
    asm volatile("ldmatrix.sync.aligned.m8n8.x4.shared.b16 {%0,%1,%2,%3}, [%4];"
        : "=r"(r[0]), "=r"(r[1]), "=r"(r[2]), "=r"(r[3]) : "r"(addr));
}

__device__ __forceinline__ uint32_t lds32(uint32_t addr) {
    uint32_t v;
    asm volatile("ld.shared.b32 %0, [%1];" : "=r"(v) : "r"(addr));
    return v;
}

// unbiased fp32 -> tf32 rounding (bit pattern stays in a b32 reg)
__device__ __forceinline__ uint32_t f2tf32(uint32_t u) {
    uint32_t r;
    asm("cvt.rna.tf32.f32 %0, %1;" : "=r"(r) : "f"(__uint_as_float(u)));
    return r;
}

__device__ __forceinline__ void mma_tf32(float d[4],
    const uint32_t a[4], uint32_t b0, uint32_t b1)
{
    asm volatile(
        "mma.sync.aligned.m16n8k8.row.col.f32.tf32.tf32.f32 "
        "{%0,%1,%2,%3}, {%4,%5,%6,%7}, {%8,%9}, {%0,%1,%2,%3};"
        : "+f"(d[0]), "+f"(d[1]), "+f"(d[2]), "+f"(d[3])
        : "r"(a[0]), "r"(a[1]), "r"(a[2]), "r"(a[3]), "r"(b0), "r"(b1));
}

// ---------------- tiny prep (token map + tile table only) -------------------
#define MBLK (MTOT / 256)             // 64
#define PREP_GRID (MBLK + 1)

__global__ __launch_bounds__(256) void prep_all(
    const int* __restrict__ scatter, const int* __restrict__ splits)
{
    int b = blockIdx.x;
    if (b < MBLK) {
        int f = b * 256 + threadIdx.x;
        g_token_of_row[scatter[f]] = f / TOPK;
    } else if (threadIdx.x == 0) {
        int cum = 0, t = 0;
        for (int e = 0; e < NEXP; e++) {
            int cnt = splits[e];
            for (int r0 = 0; r0 < cnt; r0 += BM) {
                g_tile_e[t] = e;
                g_tile_row0[t] = cum + r0;
                g_tile_rows[t] = (cnt - r0 < BM) ? (cnt - r0) : BM;
                t++;
            }
            cum += cnt;
        }
        g_njobs = t * NBLK;
        g_job = 0;
    }
}

// ---------------- main GEMM --------------------------------------------------
// Stage: A 128 rows x 128B (swizzled) + B 128 rows x 128B data (144B stride).
// 2048 x 16B cp.async, 8 per thread.
__device__ __forceinline__ void load_stage(uint32_t sbuf, int c,
                                           const float* __restrict__ x,
                                           const float* __restrict__ w,
                                           int wbase, const int* s_tok, int tid)
{
    const size_t kb = (size_t)c * BK;        // element offset of chunk start
    #pragma unroll
    for (int i = 0; i < 8; i++) {
        int o = tid + i * 256;               // 0..2047
        const char* src;
        uint32_t dst;
        if (o < 1024) {                      // A (gathered fp32 x rows)
            int r   = o >> 3;
            int seg = o & 7;
            dst = sbuf + r * ASTRIDE + (uint32_t)((seg ^ (r & 7)) << 4);
            src = (const char*)(x + (size_t)s_tok[r] * KDIM + kb) + seg * 16;
        } else {                             // B (fp32 W rows)
            int o2  = o - 1024;
            int n   = o2 >> 3;
            int seg = ((o2 & 7) - (o2 >> 3)) & 7;   // write-conflict-free perm
            dst = sbuf + OFF_B + n * BSTRIDE + (uint32_t)(seg << 4);
            src = (const char*)(w + (size_t)(wbase + n) * KDIM + kb) + seg * 16;
        }
        CPA16(dst, src);
    }
}

__global__ __launch_bounds__(256, 2) void moe_gemm_tf32(
    const float* __restrict__ x, const float* __restrict__ w,
    float* __restrict__ out)
{
    extern __shared__ char smem_raw[];
    const uint32_t stage0 = smem_to_u32(smem_raw);
    int* s_tok = (int*)(smem_raw + NSTAGE * STAGE_BYTES);
    int* s_job = (int*)(smem_raw + NSTAGE * STAGE_BYTES + 512);

    const int tid  = threadIdx.x;
    const int wid  = tid >> 5;
    const int lane = tid & 31;
    const int wm   = wid & 3;          // 4 warps along M (32 rows each)
    const int wn   = wid >> 2;         // 2 warps along N (64 cols each)

    // ---- A fragment addressing (ldmatrix-b16-on-fp32 trick) ----
    // matrix j = quadrant: j0:(m0-7,k0-3) j1:(m8-15,k0-3) j2:(m0-7,k4-7) j3:(m8-15,k4-7)
    // lane L supplies row for matrix L>>3.
    const int aq   = (lane >> 3) & 1;              // +8 rows for matrices 1,3
    const int skA  = lane >> 4;                    // +1 seg (k+4) for matrices 2,3
    uint32_t baseA[2]; int maskA[2];
    #pragma unroll
    for (int mt = 0; mt < 2; mt++) {
        int r = wm * 32 + mt * 16 + aq * 8 + (lane & 7);
        baseA[mt] = (uint32_t)(r * ASTRIDE);
        maskA[mt] = r & 7;
    }
    // ---- B fragment addressing (ld.shared.b32, conflict-free 144B stride) --
    // tf32 m16n8k8 B frag: b0 = B[k=lane&3][n=lane>>2], b1 = k+4 same n.
    const int bN = lane >> 2;          // n within 8-tile
    const int bK = lane & 3;           // k within k-step
    uint32_t baseB[8];
    #pragma unroll
    for (int nt = 0; nt < 8; nt++)
        baseB[nt] = (uint32_t)((wn * 64 + nt * 8 + bN) * BSTRIDE + bK * 4);

    const int njobs = g_njobs;

    while (true) {
        __syncthreads();                          // smem free from previous job
        if (tid == 0) *s_job = atomicAdd(&g_job, 1);
        __syncthreads();
        const int job = *s_job;
        if (job >= njobs) break;

        const int tile = job >> 3;                // NBLK = 8
        const int nb   = job & 7;
        const int nrows = g_tile_rows[tile];
        const int row0  = g_tile_row0[tile];
        const int e     = g_tile_e[tile];
        const int n0    = nb * BN;
        const int wbase = e * NDIM + n0;

        if (tid < 128)
            s_tok[tid] = (tid < nrows) ? g_token_of_row[row0 + tid] : 0;
        __syncthreads();

        float acc[2][8][4];
        #pragma unroll
        for (int mt = 0; mt < 2; mt++)
            #pragma unroll
            for (int nt = 0; nt < 8; nt++)
                #pragma unroll
                for (int q = 0; q < 4; q++)
                    acc[mt][nt][q] = 0.0f;

        // prologue: 2 stages in flight
        load_stage(stage0, 0, x, w, wbase, s_tok, tid);
        CPA_COMMIT();
        load_stage(stage0 + STAGE_BYTES, 1, x, w, wbase, s_tok, tid);
        CPA_COMMIT();

        uint32_t sbuf = stage0;
        for (int c = 0; c < NCHUNK; c++) {
            if (c < NCHUNK - 1) { CPA_WAIT1(); } else { CPA_WAIT0(); }
            __syncthreads();                      // single barrier per chunk

            #pragma unroll
            for (int ks = 0; ks < 4; ks++) {
                // mid-chunk: issue next stage's loads after 2 k-steps so the
                // post-barrier ldsm/MMA restart isn't delayed by the LDGSTS burst
                if (ks == 2 && c + 2 < NCHUNK) {
                    uint32_t nbuf = sbuf + 2 * STAGE_BYTES;
                    if (nbuf >= stage0 + 3 * STAGE_BYTES) nbuf -= 3 * STAGE_BYTES;
                    load_stage(nbuf, c + 2, x, w, wbase, s_tok, tid);
                    CPA_COMMIT();
                }

                uint32_t Af[2][4];
                #pragma unroll
                for (int mt = 0; mt < 2; mt++) {
                    const uint32_t ao = baseA[mt] +
                        (uint32_t)((((ks * 2 + skA) ^ maskA[mt])) << 4);
                    ldsm_x4(Af[mt], sbuf + ao);
                    #pragma unroll
                    for (int q = 0; q < 4; q++) Af[mt][q] = f2tf32(Af[mt][q]);
                }
                #pragma unroll
                for (int nt = 0; nt < 8; nt++) {
                    const uint32_t ba = sbuf + OFF_B + baseB[nt] +
                                        (uint32_t)(ks * 32);
                    uint32_t b0 = lds32(ba);
                    uint32_t b1 = lds32(ba + 16);   // k+4
                    b0 = f2tf32(b0);
                    b1 = f2tf32(b1);
                    mma_tf32(acc[0][nt], Af[0], b0, b1);
                    mma_tf32(acc[1][nt], Af[1], b0, b1);
                }
            }

            sbuf += STAGE_BYTES;
            if (sbuf >= stage0 + 3 * STAGE_BYTES) sbuf = stage0;
        }

        // epilogue: d-frag lane holds rows g, g+8 and cols 2t, 2t+1
        const int g = lane >> 2;
        const int t = lane & 3;
        #pragma unroll
        for (int mt = 0; mt < 2; mt++) {
            const int mBase = wm * 32 + mt * 16;
            const int m0 = mBase + g;
            const int m1 = mBase + g + 8;
            float* r0p = out + (size_t)(row0 + m0) * NDIM + n0 + wn * 64 + 2 * t;
            float* r1p = out + (size_t)(row0 + m1) * NDIM + n0 + wn * 64 + 2 * t;
            #pragma unroll
            for (int nt = 0; nt < 8; nt++) {
                if (m0 < nrows) {
                    float2 v; v.x = acc[mt][nt][0]; v.y = acc[mt][nt][1];
                    *(float2*)(r0p + nt * 8) = v;
                }
                if (m1 < nrows) {
                    float2 v; v.x = acc[mt][nt][2]; v.y = acc[mt][nt][3];
                    *(float2*)(r1p + nt * 8) = v;
                }
            }
        }
    }
}

// ---------------------------------------------------------------------------
extern "C" void kernel_launch(void* const* d_in, const int* in_sizes, int n_in,
                              void* d_out, int out_size) {
    const float* x       = (const float*)d_in[0];
    const float* weights = (const float*)d_in[1];
    const int*   scatter = (const int*)d_in[2];
    const int*   splits  = (const int*)d_in[3];
    float*       out     = (float*)d_out;
    (void)in_sizes; (void)n_in; (void)out_size;

    cudaFuncSetAttribute(moe_gemm_tf32,
                         cudaFuncAttributeMaxDynamicSharedMemorySize, SMEM_TOTAL);

    prep_all<<<PREP_GRID, 256>>>(scatter, splits);
    moe_gemm_tf32<<<304, 256, SMEM_TOTAL>>>(x, weights, out);  // 2 CTAs/SM
}

// round 13
// speedup vs baseline: 1.3316x; 1.1586x over previous
#include <cuda_runtime.h>
#include <cuda_bf16.h>
#include <cstdint>

// ===========================================================================
// MoE AG-scatter grouped GEMM via single-pass TF32 mma.sync.
//   out[s,:] = x[token(s),:] @ W[e(s),:,:]^T      (fp32 in/out)
// R13 = R12 numerics (cvt.rna tf32, rel_err 2.9e-4) with a clean feed:
//   (1) prep pre-rounds x and W to tf32 (stored as fp32, low mantissa zero)
//       -> ZERO cvt in the GEMM hot loop;
//   (2) B fragments via the ldmatrix-b16-on-fp32 trick (one ldsm.x4 yields
//       b0/b1 for two n-tiles) -> replaces 64 lds32 + 64 cvt per chunk.
// Hot loop per chunk/warp: 8 A-ldsm + 16 B-ldsm + 64 HMMA.1688 (vs R9's
// 24 ldsm + 96 HMMA.16816): 2/3 the tensor work of R9 with a leaner loop.
// Pipeline: BK=32 (4 tf32 k-steps), 3-stage cp.async, 1 bar/chunk, mid-chunk
// load placement, CTA 128x128, 8 warps 4Mx2N, 2 CTAs/SM, persistent jobs.
// ===========================================================================

#define NTOK   8192
#define TOPK   2
#define MTOT   (NTOK * TOPK)          // 16384
#define NDIM   1024
#define KDIM   1024
#define NEXP   8

#define BM     128
#define BN     128
#define BK     32                     // fp32 k per chunk = 4 tf32 k-steps
#define NCHUNK (KDIM / BK)            // 32
#define NSTAGE 3
#define NBLK   (NDIM / BN)            // 8
#define MAXTILES (MTOT / BM + NEXP)   // 136

#define ASTRIDE 128                   // A row bytes (8 x 16B segs, XOR swizzle)
#define BSTRIDE 144                   // B row bytes (128B data + 16B pad)
#define OFF_B   (128 * ASTRIDE)       // 16384
#define STAGE_BYTES (OFF_B + 128 * BSTRIDE)             // 34816
#define SMEM_TOTAL  (NSTAGE * STAGE_BYTES + 512 + 16)   // 104976

// ---------------- device-global scratch ------------------------------------
__device__ int g_token_of_row[MTOT];
__device__ int g_tile_e[MAXTILES];
__device__ int g_tile_row0[MAXTILES];
__device__ int g_tile_rows[MAXTILES];
__device__ int g_njobs;
__device__ int g_job;
__device__ __align__(16) float g_Xr[(size_t)NTOK * KDIM];            // tf32-rounded x
__device__ __align__(16) float g_Wr[(size_t)NEXP * NDIM * KDIM];     // tf32-rounded W

// ---------------- helpers ---------------------------------------------------
__device__ __forceinline__ uint32_t smem_to_u32(const void* p) {
    uint32_t a;
    asm("{ .reg .u64 t; cvta.to.shared.u64 t, %1; cvt.u32.u64 %0, t; }"
        : "=r"(a) : "l"(p));
    return a;
}

#define CPA16(dst_u32, src_ptr) \
    asm volatile("cp.async.cg.shared.global [%0], [%1], 16;" \
        :: "r"(dst_u32), "l"(src_ptr))
#define CPA_COMMIT() asm volatile("cp.async.commit_group;")
#define CPA_WAIT1()  asm volatile("cp.async.wait_group 1;")
#define CPA_WAIT0()  asm volatile("cp.async.wait_group 0;")

__device__ __forceinline__ void ldsm_x4(uint32_t r[4], uint32_t addr) {
    asm volatile("ldmatrix.sync.aligned.m8n8.x4.shared.b16 {%0,%1,%2,%3}, [%4];"
        : "=r"(r[0]), "=r"(r[1]), "=r"(r[2]), "=r"(r[3]) : "r"(addr));
}

// unbiased fp32 -> tf32 rounding
__device__ __forceinline__ float f2tf32f(float f) {
    uint32_t r;
    asm("cvt.rna.tf32.f32 %0, %1;" : "=r"(r) : "f"(f));
    return __uint_as_float(r);
}

__device__ __forceinline__ void mma_tf32(float d[4],
    const uint32_t a[4], uint32_t b0, uint32_t b1)
{
    asm volatile(
        "mma.sync.aligned.m16n8k8.row.col.f32.tf32.tf32.f32 "
        "{%0,%1,%2,%3}, {%4,%5,%6,%7}, {%8,%9}, {%0,%1,%2,%3};"
        : "+f"(d[0]), "+f"(d[1]), "+f"(d[2]), "+f"(d[3])
        : "r"(a[0]), "r"(a[1]), "r"(a[2]), "r"(a[3]), "r"(b0), "r"(b1));
}

// ---------------- fused prep -------------------------------------------------
// Blocks [0, 4096)        : round W  (8M elements, 2 float4/thread)
// Blocks [4096, 8192)     : round x  (8M elements, 2 float4/thread)
// Blocks [8192, 8256)     : token map
// Block  8256             : tile table
#define WBLK 4096
#define ABLK 4096
#define MBLK (MTOT / 256)             // 64
#define PREP_GRID (WBLK + ABLK + MBLK + 1)

__global__ __launch_bounds__(256) void prep_all(
    const float* __restrict__ x, const float* __restrict__ w,
    const int* __restrict__ scatter, const int* __restrict__ splits)
{
    int b = blockIdx.x;
    if (b < WBLK + ABLK) {
        const bool isW = (b < WBLK);
        const float* src = isW ? w : x;
        float* dst = isW ? g_Wr : g_Xr;
        size_t q  = ((size_t)(isW ? b : b - WBLK) * 512 + threadIdx.x);
        size_t o0 = q * 4;
        size_t o1 = (q + 256) * 4;
        float4 v0 = *(const float4*)(src + o0);   // both loads in flight
        float4 v1 = *(const float4*)(src + o1);
        v0.x = f2tf32f(v0.x); v0.y = f2tf32f(v0.y);
        v0.z = f2tf32f(v0.z); v0.w = f2tf32f(v0.w);
        v1.x = f2tf32f(v1.x); v1.y = f2tf32f(v1.y);
        v1.z = f2tf32f(v1.z); v1.w = f2tf32f(v1.w);
        *(float4*)(dst + o0) = v0;
        *(float4*)(dst + o1) = v1;
    } else if (b < WBLK + ABLK + MBLK) {
        int f = (b - WBLK - ABLK) * 256 + threadIdx.x;
        g_token_of_row[scatter[f]] = f / TOPK;
    } else if (threadIdx.x == 0) {
        int cum = 0, t = 0;
        for (int e = 0; e < NEXP; e++) {
            int cnt = splits[e];
            for (int r0 = 0; r0 < cnt; r0 += BM) {
                g_tile_e[t] = e;
                g_tile_row0[t] = cum + r0;
                g_tile_rows[t] = (cnt - r0 < BM) ? (cnt - r0) : BM;
                t++;
            }
            cum += cnt;
        }
        g_njobs = t * NBLK;
        g_job = 0;
    }
}

// ---------------- main GEMM --------------------------------------------------
// Stage: A 128 rows x 128B (seg^=(row&7)) + B 128 rows x 128B data (144B
// stride, linear layout). 2048 x 16B cp.async, 8 per thread.
__device__ __forceinline__ void load_stage(uint32_t sbuf, int c,
                                           int wbase, const int* s_tok, int tid)
{
    const size_t kb = (size_t)c * BK;
    #pragma unroll
    for (int i = 0; i < 8; i++) {
        int o = tid + i * 256;               // 0..2047
        const char* src;
        uint32_t dst;
        if (o < 1024) {                      // A (gathered tf32-rounded x rows)
            int r   = o >> 3;
            int seg = o & 7;
            dst = sbuf + r * ASTRIDE + (uint32_t)((seg ^ (r & 7)) << 4);
            src = (const char*)(g_Xr + (size_t)s_tok[r] * KDIM + kb) + seg * 16;
        } else {                             // B (tf32-rounded W rows)
            int o2  = o - 1024;
            int n   = o2 >> 3;
            int seg = ((o2 & 7) - (o2 >> 3)) & 7;   // write-conflict-free perm
            dst = sbuf + OFF_B + n * BSTRIDE + (uint32_t)(seg << 4);
            src = (const char*)(g_Wr + (size_t)(wbase + n) * KDIM + kb) + seg * 16;
        }
        CPA16(dst, src);
    }
}

__global__ __launch_bounds__(256, 2) void moe_gemm_tf32(float* __restrict__ out)
{
    extern __shared__ char smem_raw[];
    const uint32_t stage0 = smem_to_u32(smem_raw);
    int* s_tok = (int*)(smem_raw + NSTAGE * STAGE_BYTES);
    int* s_job = (int*)(smem_raw + NSTAGE * STAGE_BYTES + 512);

    const int tid  = threadIdx.x;
    const int wid  = tid >> 5;
    const int lane = tid & 31;
    const int wm   = wid & 3;          // 4 warps along M (32 rows each)
    const int wn   = wid >> 2;         // 2 warps along N (64 cols each)

    // ---- A fragment addressing (ldmatrix-b16-on-fp32, validated in R12) ----
    const int aq   = (lane >> 3) & 1;              // +8 rows for matrices 1,3
    const int skA  = lane >> 4;                    // +1 seg (k+4) for mats 2,3
    uint32_t baseA[2]; int maskA[2];
    #pragma unroll
    for (int mt = 0; mt < 2; mt++) {
        int r = wm * 32 + mt * 16 + aq * 8 + (lane & 7);
        baseA[mt] = (uint32_t)(r * ASTRIDE);
        maskA[mt] = r & 7;
    }
    // ---- B fragment addressing (ldmatrix-b16-on-fp32, NEW) ----
    // ldsm.x4 for n-tile pair j: matrices {0,1} = nt=2j segs {2ks, 2ks+1};
    //                            matrices {2,3} = nt=2j+1 same segs.
    // lane L serves matrix g=L>>3, row n = base + (L&7).
    const int bg   = lane >> 3;                    // matrix group 0..3
    const uint32_t baseB = (uint32_t)(
        (wn * 64 + ((bg >> 1) ? 8 : 0) + (lane & 7)) * BSTRIDE + (bg & 1) * 16);

    const int njobs = g_njobs;

    while (true) {
        __syncthreads();                          // smem free from previous job
        if (tid == 0) *s_job = atomicAdd(&g_job, 1);
        __syncthreads();
        const int job = *s_job;
        if (job >= njobs) break;

        const int tile = job >> 3;                // NBLK = 8
        const int nb   = job & 7;
        const int nrows = g_tile_rows[tile];
        const int row0  = g_tile_row0[tile];
        const int e     = g_tile_e[tile];
        const int n0    = nb * BN;
        const int wbase = e * NDIM + n0;

        if (tid < 128)
            s_tok[tid] = (tid < nrows) ? g_token_of_row[row0 + tid] : 0;
        __syncthreads();

        float acc[2][8][4];
        #pragma unroll
        for (int mt = 0; mt < 2; mt++)
            #pragma unroll
            for (int nt = 0; nt < 8; nt++)
                #pragma unroll
                for (int q = 0; q < 4; q++)
                    acc[mt][nt][q] = 0.0f;

        // prologue: 2 stages in flight
        load_stage(stage0, 0, wbase, s_tok, tid);
        CPA_COMMIT();
        load_stage(stage0 + STAGE_BYTES, 1, wbase, s_tok, tid);
        CPA_COMMIT();

        uint32_t sbuf = stage0;
        for (int c = 0; c < NCHUNK; c++) {
            if (c < NCHUNK - 1) { CPA_WAIT1(); } else { CPA_WAIT0(); }
            __syncthreads();                      // single barrier per chunk

            #pragma unroll
            for (int ks = 0; ks < 4; ks++) {
                // mid-chunk load placement (after 2 k-steps)
                if (ks == 2 && c + 2 < NCHUNK) {
                    uint32_t nbuf = sbuf + 2 * STAGE_BYTES;
                    if (nbuf >= stage0 + 3 * STAGE_BYTES) nbuf -= 3 * STAGE_BYTES;
                    load_stage(nbuf, c + 2, wbase, s_tok, tid);
                    CPA_COMMIT();
                }

                uint32_t Af[2][4];
                #pragma unroll
                for (int mt = 0; mt < 2; mt++) {
                    const uint32_t ao = baseA[mt] +
                        (uint32_t)(((ks * 2 + skA) ^ maskA[mt]) << 4);
                    ldsm_x4(Af[mt], sbuf + ao);
                }
                const uint32_t bks = sbuf + OFF_B + baseB + (uint32_t)(ks * 32);
                #pragma unroll
                for (int j = 0; j < 4; j++) {
                    uint32_t Bf[4];                       // b0,b1 of nt=2j; 2j+1
                    ldsm_x4(Bf, bks + (uint32_t)(j * 16 * BSTRIDE));
                    #pragma unroll
                    for (int mt = 0; mt < 2; mt++) {
                        mma_tf32(acc[mt][2 * j],     Af[mt], Bf[0], Bf[1]);
                        mma_tf32(acc[mt][2 * j + 1], Af[mt], Bf[2], Bf[3]);
                    }
                }
            }

            sbuf += STAGE_BYTES;
            if (sbuf >= stage0 + 3 * STAGE_BYTES) sbuf = stage0;
        }

        // epilogue: d-frag lane holds rows g, g+8 and cols 2t, 2t+1
        const int g = lane >> 2;
        const int t = lane & 3;
        #pragma unroll
        for (int mt = 0; mt < 2; mt++) {
            const int mBase = wm * 32 + mt * 16;
            const int m0 = mBase + g;
            const int m1 = mBase + g + 8;
            float* r0p = out + (size_t)(row0 + m0) * NDIM + n0 + wn * 64 + 2 * t;
            float* r1p = out + (size_t)(row0 + m1) * NDIM + n0 + wn * 64 + 2 * t;
            #pragma unroll
            for (int nt = 0; nt < 8; nt++) {
                if (m0 < nrows) {
                    float2 v; v.x = acc[mt][nt][0]; v.y = acc[mt][nt][1];
                    *(float2*)(r0p + nt * 8) = v;
                }
                if (m1 < nrows) {
                    float2 v; v.x = acc[mt][nt][2]; v.y = acc[mt][nt][3];
                    *(float2*)(r1p + nt * 8) = v;
                }
            }
        }
    }
}

// ---------------------------------------------------------------------------
extern "C" void kernel_launch(void* const* d_in, const int* in_sizes, int n_in,
                              void* d_out, int out_size) {
    const float* x       = (const float*)d_in[0];
    const float* weights = (const float*)d_in[1];
    const int*   scatter = (const int*)d_in[2];
    const int*   splits  = (const int*)d_in[3];
    float*       out     = (float*)d_out;
    (void)in_sizes; (void)n_in; (void)out_size;

    cudaFuncSetAttribute(moe_gemm_tf32,
                         cudaFuncAttributeMaxDynamicSharedMemorySize, SMEM_TOTAL);

    prep_all<<<PREP_GRID, 256>>>(x, weights, scatter, splits);
    moe_gemm_tf32<<<304, 256, SMEM_TOTAL>>>(out);   // persistent, 2 CTAs/SM
}

// round 14
// speedup vs baseline: 1.3367x; 1.0038x over previous
#include <cuda_runtime.h>
#include <cuda_bf16.h>
#include <cstdint>

// ===========================================================================
// MoE AG-scatter grouped GEMM via single-pass TF32 mma.sync.
//   out[s,:] = x[token(s),:] @ W[e(s),:,:]^T      (fp32 in/out)
// R14 = R13 (tf32, pre-rounded operands, ldmatrix-b16-on-fp32 A and B
//   fragments, 3-stage cp.async, 1 bar/chunk, mid-chunk loads, CTA 128x128,
//   8 warps 4Mx2N, 2 CTAs/SM, persistent jobs) minus the x pre-round pass:
//   A is gathered from the ORIGINAL fp32 x and rounded in-register with
//   cvt.rna.tf32 on the 8 A-fragment regs per k-step (32 cvts/warp-chunk --
//   tiny vs R12's 96 cvt + 64 lds32). W stays pre-rounded (B frags clean).
//   prep traffic drops 128MB -> 64MB (~18us -> ~10us). Numerics identical.
// ===========================================================================

#define NTOK   8192
#define TOPK   2
#define MTOT   (NTOK * TOPK)          // 16384
#define NDIM   1024
#define KDIM   1024
#define NEXP   8

#define BM     128
#define BN     128
#define BK     32                     // fp32 k per chunk = 4 tf32 k-steps
#define NCHUNK (KDIM / BK)            // 32
#define NSTAGE 3
#define NBLK   (NDIM / BN)            // 8
#define MAXTILES (MTOT / BM + NEXP)   // 136

#define ASTRIDE 128                   // A row bytes (8 x 16B segs, XOR swizzle)
#define BSTRIDE 144                   // B row bytes (128B data + 16B pad)
#define OFF_B   (128 * ASTRIDE)       // 16384
#define STAGE_BYTES (OFF_B + 128 * BSTRIDE)             // 34816
#define SMEM_TOTAL  (NSTAGE * STAGE_BYTES + 512 + 16)   // 104976

// ---------------- device-global scratch ------------------------------------
__device__ int g_token_of_row[MTOT];
__device__ int g_tile_e[MAXTILES];
__device__ int g_tile_row0[MAXTILES];
__device__ int g_tile_rows[MAXTILES];
__device__ int g_njobs;
__device__ int g_job;
__device__ __align__(16) float g_Wr[(size_t)NEXP * NDIM * KDIM];  // tf32-rounded W

// ---------------- helpers ---------------------------------------------------
__device__ __forceinline__ uint32_t smem_to_u32(const void* p) {
    uint32_t a;
    asm("{ .reg .u64 t; cvta.to.shared.u64 t, %1; cvt.u32.u64 %0, t; }"
        : "=r"(a) : "l"(p));
    return a;
}

#define CPA16(dst_u32, src_ptr) \
    asm volatile("cp.async.cg.shared.global [%0], [%1], 16;" \
        :: "r"(dst_u32), "l"(src_ptr))
#define CPA_COMMIT() asm volatile("cp.async.commit_group;")
#define CPA_WAIT1()  asm volatile("cp.async.wait_group 1;")
#define CPA_WAIT0()  asm volatile("cp.async.wait_group 0;")

__device__ __forceinline__ void ldsm_x4(uint32_t r[4], uint32_t addr) {
    asm volatile("ldmatrix.sync.aligned.m8n8.x4.shared.b16 {%0,%1,%2,%3}, [%4];"
        : "=r"(r[0]), "=r"(r[1]), "=r"(r[2]), "=r"(r[3]) : "r"(addr));
}

// unbiased fp32 -> tf32 rounding, bit pattern in b32 reg
__device__ __forceinline__ uint32_t f2tf32(uint32_t u) {
    uint32_t r;
    asm("cvt.rna.tf32.f32 %0, %1;" : "=r"(r) : "f"(__uint_as_float(u)));
    return r;
}
__device__ __forceinline__ float f2tf32f(float f) {
    uint32_t r;
    asm("cvt.rna.tf32.f32 %0, %1;" : "=r"(r) : "f"(f));
    return __uint_as_float(r);
}

__device__ __forceinline__ void mma_tf32(float d[4],
    const uint32_t a[4], uint32_t b0, uint32_t b1)
{
    asm volatile(
        "mma.sync.aligned.m16n8k8.row.col.f32.tf32.tf32.f32 "
        "{%0,%1,%2,%3}, {%4,%5,%6,%7}, {%8,%9}, {%0,%1,%2,%3};"
        : "+f"(d[0]), "+f"(d[1]), "+f"(d[2]), "+f"(d[3])
        : "r"(a[0]), "r"(a[1]), "r"(a[2]), "r"(a[3]), "r"(b0), "r"(b1));
}

// ---------------- prep: round W + token map + tile table --------------------
// Blocks [0, 4096)     : round W (8.39M floats, 2 float4/thread, MLP=2)
// Blocks [4096, 4160)  : token map
// Block  4160          : tile table
#define WBLK 4096
#define MBLK (MTOT / 256)             // 64
#define PREP_GRID (WBLK + MBLK + 1)

__global__ __launch_bounds__(256) void prep_all(
    const float* __restrict__ w,
    const int* __restrict__ scatter, const int* __restrict__ splits)
{
    int b = blockIdx.x;
    if (b < WBLK) {
        size_t q  = ((size_t)b * 512 + threadIdx.x);
        size_t o0 = q * 4;
        size_t o1 = (q + 256) * 4;
        float4 v0 = *(const float4*)(w + o0);   // both loads in flight
        float4 v1 = *(const float4*)(w + o1);
        v0.x = f2tf32f(v0.x); v0.y = f2tf32f(v0.y);
        v0.z = f2tf32f(v0.z); v0.w = f2tf32f(v0.w);
        v1.x = f2tf32f(v1.x); v1.y = f2tf32f(v1.y);
        v1.z = f2tf32f(v1.z); v1.w = f2tf32f(v1.w);
        *(float4*)(g_Wr + o0) = v0;
        *(float4*)(g_Wr + o1) = v1;
    } else if (b < WBLK + MBLK) {
        int f = (b - WBLK) * 256 + threadIdx.x;
        g_token_of_row[scatter[f]] = f / TOPK;
    } else if (threadIdx.x == 0) {
        int cum = 0, t = 0;
        for (int e = 0; e < NEXP; e++) {
            int cnt = splits[e];
            for (int r0 = 0; r0 < cnt; r0 += BM) {
                g_tile_e[t] = e;
                g_tile_row0[t] = cum + r0;
                g_tile_rows[t] = (cnt - r0 < BM) ? (cnt - r0) : BM;
                t++;
            }
            cum += cnt;
        }
        g_njobs = t * NBLK;
        g_job = 0;
    }
}

// ---------------- main GEMM --------------------------------------------------
// Stage: A 128 rows x 128B (seg^=(row&7)), gathered from ORIGINAL x;
//        B 128 rows x 128B data (144B stride) from pre-rounded g_Wr.
__device__ __forceinline__ void load_stage(uint32_t sbuf, int c,
                                           const float* __restrict__ x,
                                           int wbase, const int* s_tok, int tid)
{
    const size_t kb = (size_t)c * BK;
    #pragma unroll
    for (int i = 0; i < 8; i++) {
        int o = tid + i * 256;               // 0..2047
        const char* src;
        uint32_t dst;
        if (o < 1024) {                      // A (gathered raw fp32 x rows)
            int r   = o >> 3;
            int seg = o & 7;
            dst = sbuf + r * ASTRIDE + (uint32_t)((seg ^ (r & 7)) << 4);
            src = (const char*)(x + (size_t)s_tok[r] * KDIM + kb) + seg * 16;
        } else {                             // B (tf32-rounded W rows)
            int o2  = o - 1024;
            int n   = o2 >> 3;
            int seg = ((o2 & 7) - (o2 >> 3)) & 7;   // write-conflict-free perm
            dst = sbuf + OFF_B + n * BSTRIDE + (uint32_t)(seg << 4);
            src = (const char*)(g_Wr + (size_t)(wbase + n) * KDIM + kb) + seg * 16;
        }
        CPA16(dst, src);
    }
}

__global__ __launch_bounds__(256, 2) void moe_gemm_tf32(
    const float* __restrict__ x, float* __restrict__ out)
{
    extern __shared__ char smem_raw[];
    const uint32_t stage0 = smem_to_u32(smem_raw);
    int* s_tok = (int*)(smem_raw + NSTAGE * STAGE_BYTES);
    int* s_job = (int*)(smem_raw + NSTAGE * STAGE_BYTES + 512);

    const int tid  = threadIdx.x;
    const int wid  = tid >> 5;
    const int lane = tid & 31;
    const int wm   = wid & 3;          // 4 warps along M (32 rows each)
    const int wn   = wid >> 2;         // 2 warps along N (64 cols each)

    // ---- A fragment addressing (ldmatrix-b16-on-fp32) ----
    const int aq   = (lane >> 3) & 1;              // +8 rows for matrices 1,3
    const int skA  = lane >> 4;                    // +1 seg (k+4) for mats 2,3
    uint32_t baseA[2]; int maskA[2];
    #pragma unroll
    for (int mt = 0; mt < 2; mt++) {
        int r = wm * 32 + mt * 16 + aq * 8 + (lane & 7);
        baseA[mt] = (uint32_t)(r * ASTRIDE);
        maskA[mt] = r & 7;
    }
    // ---- B fragment addressing (ldmatrix-b16-on-fp32) ----
    const int bg   = lane >> 3;                    // matrix group 0..3
    const uint32_t baseB = (uint32_t)(
        (wn * 64 + ((bg >> 1) ? 8 : 0) + (lane & 7)) * BSTRIDE + (bg & 1) * 16);

    const int njobs = g_njobs;

    while (true) {
        __syncthreads();                          // smem free from previous job
        if (tid == 0) *s_job = atomicAdd(&g_job, 1);
        __syncthreads();
        const int job = *s_job;
        if (job >= njobs) break;

        const int tile = job >> 3;                // NBLK = 8
        const int nb   = job & 7;
        const int nrows = g_tile_rows[tile];
        const int row0  = g_tile_row0[tile];
        const int e     = g_tile_e[tile];
        const int n0    = nb * BN;
        const int wbase = e * NDIM + n0;

        if (tid < 128)
            s_tok[tid] = (tid < nrows) ? g_token_of_row[row0 + tid] : 0;
        __syncthreads();

        float acc[2][8][4];
        #pragma unroll
        for (int mt = 0; mt < 2; mt++)
            #pragma unroll
            for (int nt = 0; nt < 8; nt++)
                #pragma unroll
                for (int q = 0; q < 4; q++)
                    acc[mt][nt][q] = 0.0f;

        // prologue: 2 stages in flight
        load_stage(stage0, 0, x, wbase, s_tok, tid);
        CPA_COMMIT();
        load_stage(stage0 + STAGE_BYTES, 1, x, wbase, s_tok, tid);
        CPA_COMMIT();

        uint32_t sbuf = stage0;
        for (int c = 0; c < NCHUNK; c++) {
            if (c < NCHUNK - 1) { CPA_WAIT1(); } else { CPA_WAIT0(); }
            __syncthreads();                      // single barrier per chunk

            #pragma unroll
            for (int ks = 0; ks < 4; ks++) {
                // mid-chunk load placement (after 2 k-steps)
                if (ks == 2 && c + 2 < NCHUNK) {
                    uint32_t nbuf = sbuf + 2 * STAGE_BYTES;
                    if (nbuf >= stage0 + 3 * STAGE_BYTES) nbuf -= 3 * STAGE_BYTES;
                    load_stage(nbuf, c + 2, x, wbase, s_tok, tid);
                    CPA_COMMIT();
                }

                uint32_t Af[2][4];
                #pragma unroll
                for (int mt = 0; mt < 2; mt++) {
                    const uint32_t ao = baseA[mt] +
                        (uint32_t)(((ks * 2 + skA) ^ maskA[mt]) << 4);
                    ldsm_x4(Af[mt], sbuf + ao);
                    #pragma unroll
                    for (int q = 0; q < 4; q++) Af[mt][q] = f2tf32(Af[mt][q]);
                }
                const uint32_t bks = sbuf + OFF_B + baseB + (uint32_t)(ks * 32);
                #pragma unroll
                for (int j = 0; j < 4; j++) {
                    uint32_t Bf[4];                       // b0,b1 of nt=2j; 2j+1
                    ldsm_x4(Bf, bks + (uint32_t)(j * 16 * BSTRIDE));
                    #pragma unroll
                    for (int mt = 0; mt < 2; mt++) {
                        mma_tf32(acc[mt][2 * j],     Af[mt], Bf[0], Bf[1]);
                        mma_tf32(acc[mt][2 * j + 1], Af[mt], Bf[2], Bf[3]);
                    }
                }
            }

            sbuf += STAGE_BYTES;
            if (sbuf >= stage0 + 3 * STAGE_BYTES) sbuf = stage0;
        }

        // epilogue: d-frag lane holds rows g, g+8 and cols 2t, 2t+1
        const int g = lane >> 2;
        const int t = lane & 3;
        #pragma unroll
        for (int mt = 0; mt < 2; mt++) {
            const int mBase = wm * 32 + mt * 16;
            const int m0 = mBase + g;
            const int m1 = mBase + g + 8;
            float* r0p = out + (size_t)(row0 + m0) * NDIM + n0 + wn * 64 + 2 * t;
            float* r1p = out + (size_t)(row0 + m1) * NDIM + n0 + wn * 64 + 2 * t;
            #pragma unroll
            for (int nt = 0; nt < 8; nt++) {
                if (m0 < nrows) {
                    float2 v; v.x = acc[mt][nt][0]; v.y = acc[mt][nt][1];
                    *(float2*)(r0p + nt * 8) = v;
                }
                if (m1 < nrows) {
                    float2 v; v.x = acc[mt][nt][2]; v.y = acc[mt][nt][3];
                    *(float2*)(r1p + nt * 8) = v;
                }
            }
        }
    }
}

// ---------------------------------------------------------------------------
extern "C" void kernel_launch(void* const* d_in, const int* in_sizes, int n_in,
                              void* d_out, int out_size) {
    const float* x       = (const float*)d_in[0];
    const float* weights = (const float*)d_in[1];
    const int*   scatter = (const int*)d_in[2];
    const int*   splits  = (const int*)d_in[3];
    float*       out     = (float*)d_out;
    (void)in_sizes; (void)n_in; (void)out_size;

    cudaFuncSetAttribute(moe_gemm_tf32,
                         cudaFuncAttributeMaxDynamicSharedMemorySize, SMEM_TOTAL);

    prep_all<<<PREP_GRID, 256>>>(weights, scatter, splits);
    moe_gemm_tf32<<<304, 256, SMEM_TOTAL>>>(x, out);   // persistent, 2 CTAs/SM
}

// round 15
// speedup vs baseline: 1.3925x; 1.0418x over previous
#include <cuda_runtime.h>
#include <cuda_bf16.h>
#include <cstdint>

// ===========================================================================
// MoE AG-scatter grouped GEMM via single-pass TF32 mma.sync.
//   out[s,:] = x[token(s),:] @ W[e(s),:,:]^T      (fp32 in/out)
// R15 = R13's GEMM loop verbatim (no in-loop cvt; 173.8us measured) fed with
//   RAW fp32 A (hardware tf32 MMA ignores the low 13 mantissa bits =
//   truncation) + R14's W-only prep, where W is scaled by (1 + 2^-11*ln2)
//   BEFORE rna rounding to cancel A's coherent truncation bias
//   (E[trunc loss] = 2^-11 * E[1/m] ~= 3.38e-4). Residual error is zero-mean
//   noise ~2.5e-4. No x pre-round pass, no hot-loop cvt: both measured
//   halves (173.8 GEMM + 11.1 prep) compose.
// Pipeline: BK=32 (4 tf32 k-steps), 3-stage cp.async, 1 bar/chunk, mid-chunk
// loads, CTA 128x128, 8 warps 4Mx2N, ldmatrix-b16-on-fp32 A and B fragments,
// 2 CTAs/SM, persistent job loop.
// ===========================================================================

#define NTOK   8192
#define TOPK   2
#define MTOT   (NTOK * TOPK)          // 16384
#define NDIM   1024
#define KDIM   1024
#define NEXP   8

#define BM     128
#define BN     128
#define BK     32                     // fp32 k per chunk = 4 tf32 k-steps
#define NCHUNK (KDIM / BK)            // 32
#define NSTAGE 3
#define NBLK   (NDIM / BN)            // 8
#define MAXTILES (MTOT / BM + NEXP)   // 136

#define ASTRIDE 128                   // A row bytes (8 x 16B segs, XOR swizzle)
#define BSTRIDE 144                   // B row bytes (128B data + 16B pad)
#define OFF_B   (128 * ASTRIDE)       // 16384
#define STAGE_BYTES (OFF_B + 128 * BSTRIDE)             // 34816
#define SMEM_TOTAL  (NSTAGE * STAGE_BYTES + 512 + 16)   // 104976

// compensation for A-side tf32 truncation: 1 + 2^-11 * ln(2)
#define WCOMP 1.000338350f

// ---------------- device-global scratch ------------------------------------
__device__ int g_token_of_row[MTOT];
__device__ int g_tile_e[MAXTILES];
__device__ int g_tile_row0[MAXTILES];
__device__ int g_tile_rows[MAXTILES];
__device__ int g_njobs;
__device__ int g_job;
__device__ __align__(16) float g_Wr[(size_t)NEXP * NDIM * KDIM];  // comp+rounded W

// ---------------- helpers ---------------------------------------------------
__device__ __forceinline__ uint32_t smem_to_u32(const void* p) {
    uint32_t a;
    asm("{ .reg .u64 t; cvta.to.shared.u64 t, %1; cvt.u32.u64 %0, t; }"
        : "=r"(a) : "l"(p));
    return a;
}

#define CPA16(dst_u32, src_ptr) \
    asm volatile("cp.async.cg.shared.global [%0], [%1], 16;" \
        :: "r"(dst_u32), "l"(src_ptr))
#define CPA_COMMIT() asm volatile("cp.async.commit_group;")
#define CPA_WAIT1()  asm volatile("cp.async.wait_group 1;")
#define CPA_WAIT0()  asm volatile("cp.async.wait_group 0;")

__device__ __forceinline__ void ldsm_x4(uint32_t r[4], uint32_t addr) {
    asm volatile("ldmatrix.sync.aligned.m8n8.x4.shared.b16 {%0,%1,%2,%3}, [%4];"
        : "=r"(r[0]), "=r"(r[1]), "=r"(r[2]), "=r"(r[3]) : "r"(addr));
}

// unbiased fp32 -> tf32 rounding
__device__ __forceinline__ float f2tf32f(float f) {
    uint32_t r;
    asm("cvt.rna.tf32.f32 %0, %1;" : "=r"(r) : "f"(f));
    return __uint_as_float(r);
}

__device__ __forceinline__ void mma_tf32(float d[4],
    const uint32_t a[4], uint32_t b0, uint32_t b1)
{
    asm volatile(
        "mma.sync.aligned.m16n8k8.row.col.f32.tf32.tf32.f32 "
        "{%0,%1,%2,%3}, {%4,%5,%6,%7}, {%8,%9}, {%0,%1,%2,%3};"
        : "+f"(d[0]), "+f"(d[1]), "+f"(d[2]), "+f"(d[3])
        : "r"(a[0]), "r"(a[1]), "r"(a[2]), "r"(a[3]), "r"(b0), "r"(b1));
}

// ---------------- prep: compensate+round W, token map, tile table -----------
#define WBLK 4096
#define MBLK (MTOT / 256)             // 64
#define PREP_GRID (WBLK + MBLK + 1)

__global__ __launch_bounds__(256) void prep_all(
    const float* __restrict__ w,
    const int* __restrict__ scatter, const int* __restrict__ splits)
{
    int b = blockIdx.x;
    if (b < WBLK) {
        size_t q  = ((size_t)b * 512 + threadIdx.x);
        size_t o0 = q * 4;
        size_t o1 = (q + 256) * 4;
        float4 v0 = *(const float4*)(w + o0);   // both loads in flight
        float4 v1 = *(const float4*)(w + o1);
        v0.x = f2tf32f(v0.x * WCOMP); v0.y = f2tf32f(v0.y * WCOMP);
        v0.z = f2tf32f(v0.z * WCOMP); v0.w = f2tf32f(v0.w * WCOMP);
        v1.x = f2tf32f(v1.x * WCOMP); v1.y = f2tf32f(v1.y * WCOMP);
        v1.z = f2tf32f(v1.z * WCOMP); v1.w = f2tf32f(v1.w * WCOMP);
        *(float4*)(g_Wr + o0) = v0;
        *(float4*)(g_Wr + o1) = v1;
    } else if (b < WBLK + MBLK) {
        int f = (b - WBLK) * 256 + threadIdx.x;
        g_token_of_row[scatter[f]] = f / TOPK;
    } else if (threadIdx.x == 0) {
        int cum = 0, t = 0;
        for (int e = 0; e < NEXP; e++) {
            int cnt = splits[e];
            for (int r0 = 0; r0 < cnt; r0 += BM) {
                g_tile_e[t] = e;
                g_tile_row0[t] = cum + r0;
                g_tile_rows[t] = (cnt - r0 < BM) ? (cnt - r0) : BM;
                t++;
            }
            cum += cnt;
        }
        g_njobs = t * NBLK;
        g_job = 0;
    }
}

// ---------------- main GEMM --------------------------------------------------
// Stage: A 128 rows x 128B (seg^=(row&7)), gathered RAW from x;
//        B 128 rows x 128B data (144B stride) from compensated g_Wr.
__device__ __forceinline__ void load_stage(uint32_t sbuf, int c,
                                           const float* __restrict__ x,
                                           int wbase, const int* s_tok, int tid)
{
    const size_t kb = (size_t)c * BK;
    #pragma unroll
    for (int i = 0; i < 8; i++) {
        int o = tid + i * 256;               // 0..2047
        const char* src;
        uint32_t dst;
        if (o < 1024) {                      // A (gathered raw fp32 x rows)
            int r   = o >> 3;
            int seg = o & 7;
            dst = sbuf + r * ASTRIDE + (uint32_t)((seg ^ (r & 7)) << 4);
            src = (const char*)(x + (size_t)s_tok[r] * KDIM + kb) + seg * 16;
        } else {                             // B (compensated tf32 W rows)
            int o2  = o - 1024;
            int n   = o2 >> 3;
            int seg = ((o2 & 7) - (o2 >> 3)) & 7;   // write-conflict-free perm
            dst = sbuf + OFF_B + n * BSTRIDE + (uint32_t)(seg << 4);
            src = (const char*)(g_Wr + (size_t)(wbase + n) * KDIM + kb) + seg * 16;
        }
        CPA16(dst, src);
    }
}

__global__ __launch_bounds__(256, 2) void moe_gemm_tf32(
    const float* __restrict__ x, float* __restrict__ out)
{
    extern __shared__ char smem_raw[];
    const uint32_t stage0 = smem_to_u32(smem_raw);
    int* s_tok = (int*)(smem_raw + NSTAGE * STAGE_BYTES);
    int* s_job = (int*)(smem_raw + NSTAGE * STAGE_BYTES + 512);

    const int tid  = threadIdx.x;
    const int wid  = tid >> 5;
    const int lane = tid & 31;
    const int wm   = wid & 3;          // 4 warps along M (32 rows each)
    const int wn   = wid >> 2;         // 2 warps along N (64 cols each)

    // ---- A fragment addressing (ldmatrix-b16-on-fp32) ----
    const int aq   = (lane >> 3) & 1;              // +8 rows for matrices 1,3
    const int skA  = lane >> 4;                    // +1 seg (k+4) for mats 2,3
    uint32_t baseA[2]; int maskA[2];
    #pragma unroll
    for (int mt = 0; mt < 2; mt++) {
        int r = wm * 32 + mt * 16 + aq * 8 + (lane & 7);
        baseA[mt] = (uint32_t)(r * ASTRIDE);
        maskA[mt] = r & 7;
    }
    // ---- B fragment addressing (ldmatrix-b16-on-fp32) ----
    const int bg   = lane >> 3;                    // matrix group 0..3
    const uint32_t baseB = (uint32_t)(
        (wn * 64 + ((bg >> 1) ? 8 : 0) + (lane & 7)) * BSTRIDE + (bg & 1) * 16);

    const int njobs = g_njobs;

    while (true) {
        __syncthreads();                          // smem free from previous job
        if (tid == 0) *s_job = atomicAdd(&g_job, 1);
        __syncthreads();
        const int job = *s_job;
        if (job >= njobs) break;

        const int tile = job >> 3;                // NBLK = 8
        const int nb   = job & 7;
        const int nrows = g_tile_rows[tile];
        const int row0  = g_tile_row0[tile];
        const int e     = g_tile_e[tile];
        const int n0    = nb * BN;
        const int wbase = e * NDIM + n0;

        if (tid < 128)
            s_tok[tid] = (tid < nrows) ? g_token_of_row[row0 + tid] : 0;
        __syncthreads();

        float acc[2][8][4];
        #pragma unroll
        for (int mt = 0; mt < 2; mt++)
            #pragma unroll
            for (int nt = 0; nt < 8; nt++)
                #pragma unroll
                for (int q = 0; q < 4; q++)
                    acc[mt][nt][q] = 0.0f;

        // prologue: 2 stages in flight
        load_stage(stage0, 0, x, wbase, s_tok, tid);
        CPA_COMMIT();
        load_stage(stage0 + STAGE_BYTES, 1, x, wbase, s_tok, tid);
        CPA_COMMIT();

        uint32_t sbuf = stage0;
        for (int c = 0; c < NCHUNK; c++) {
            if (c < NCHUNK - 1) { CPA_WAIT1(); } else { CPA_WAIT0(); }
            __syncthreads();                      // single barrier per chunk

            #pragma unroll
            for (int ks = 0; ks < 4; ks++) {
                // mid-chunk load placement (after 2 k-steps)
                if (ks == 2 && c + 2 < NCHUNK) {
                    uint32_t nbuf = sbuf + 2 * STAGE_BYTES;
                    if (nbuf >= stage0 + 3 * STAGE_BYTES) nbuf -= 3 * STAGE_BYTES;
                    load_stage(nbuf, c + 2, x, wbase, s_tok, tid);
                    CPA_COMMIT();
                }

                uint32_t Af[2][4];
                #pragma unroll
                for (int mt = 0; mt < 2; mt++) {
                    const uint32_t ao = baseA[mt] +
                        (uint32_t)(((ks * 2 + skA) ^ maskA[mt]) << 4);
                    ldsm_x4(Af[mt], sbuf + ao);   // raw fp32; HW truncates to tf32
                }
                const uint32_t bks = sbuf + OFF_B + baseB + (uint32_t)(ks * 32);
                #pragma unroll
                for (int j = 0; j < 4; j++) {
                    uint32_t Bf[4];               // b0,b1 of nt=2j; 2j+1
                    ldsm_x4(Bf, bks + (uint32_t)(j * 16 * BSTRIDE));
                    #pragma unroll
                    for (int mt = 0; mt < 2; mt++) {
                        mma_tf32(acc[mt][2 * j],     Af[mt], Bf[0], Bf[1]);
                        mma_tf32(acc[mt][2 * j + 1], Af[mt], Bf[2], Bf[3]);
                    }
                }
            }

            sbuf += STAGE_BYTES;
            if (sbuf >= stage0 + 3 * STAGE_BYTES) sbuf = stage0;
        }

        // epilogue: d-frag lane holds rows g, g+8 and cols 2t, 2t+1
        const int g = lane >> 2;
        const int t = lane & 3;
        #pragma unroll
        for (int mt = 0; mt < 2; mt++) {
            const int mBase = wm * 32 + mt * 16;
            const int m0 = mBase + g;
            const int m1 = mBase + g + 8;
            float* r0p = out + (size_t)(row0 + m0) * NDIM + n0 + wn * 64 + 2 * t;
            float* r1p = out + (size_t)(row0 + m1) * NDIM + n0 + wn * 64 + 2 * t;
            #pragma unroll
            for (int nt = 0; nt < 8; nt++) {
                if (m0 < nrows) {
                    float2 v; v.x = acc[mt][nt][0]; v.y = acc[mt][nt][1];
                    *(float2*)(r0p + nt * 8) = v;
                }
                if (m1 < nrows) {
                    float2 v; v.x = acc[mt][nt][2]; v.y = acc[mt][nt][3];
                    *(float2*)(r1p + nt * 8) = v;
                }
            }
        }
    }
}

// ---------------------------------------------------------------------------
extern "C" void kernel_launch(void* const* d_in, const int* in_sizes, int n_in,
                              void* d_out, int out_size) {
    const float* x       = (const float*)d_in[0];
    const float* weights = (const float*)d_in[1];
    const int*   scatter = (const int*)d_in[2];
    const int*   splits  = (const int*)d_in[3];
    float*       out     = (float*)d_out;
    (void)in_sizes; (void)n_in; (void)out_size;

    cudaFuncSetAttribute(moe_gemm_tf32,
                         cudaFuncAttributeMaxDynamicSharedMemorySize, SMEM_TOTAL);

    prep_all<<<PREP_GRID, 256>>>(weights, scatter, splits);
    moe_gemm_tf32<<<304, 256, SMEM_TOTAL>>>(x, out);   // persistent, 2 CTAs/SM
}

// round 16
// speedup vs baseline: 1.4427x; 1.0361x over previous
#include <cuda_runtime.h>
#include <cuda_bf16.h>
#include <cstdint>

// ===========================================================================
// MoE AG-scatter grouped GEMM via single-pass TF32 mma.sync.
//   out[s,:] = x[token(s),:] @ W[e(s),:,:]^T      (fp32 in/out)
// R16 = R15's GEMM loop verbatim (173.8us measured) fed with RAW fp32 on
//   BOTH sides (hardware tf32 MMA truncates the low 13 mantissa bits).
//   The doubled coherent truncation bias ((1-c)^2, c = 2^-11 * E[frac/m]
//   ~= 3.52e-4 for log-uniform mantissas) is cancelled by ONE epilogue FMUL
//   per accumulator: scale = 1 + 2c = 1.000704. De-biased truncation noise
//   sigma (2^-11 / 2sqrt3 ~ 1.4e-4/side) equals rna noise, so rel_err stays
//   in the measured ~3e-4 regime. Data prep is GONE (no W round-trip, no
//   g_Wr buffer): prep = token map + tile table only (~2us).
// Pipeline: BK=32 (4 tf32 k-steps), 3-stage cp.async, 1 bar/chunk, mid-chunk
// loads, CTA 128x128, 8 warps 4Mx2N, ldmatrix-b16-on-fp32 A and B fragments,
// 2 CTAs/SM, persistent job loop.
// ===========================================================================

#define NTOK   8192
#define TOPK   2
#define MTOT   (NTOK * TOPK)          // 16384
#define NDIM   1024
#define KDIM   1024
#define NEXP   8

#define BM     128
#define BN     128
#define BK     32                     // fp32 k per chunk = 4 tf32 k-steps
#define NCHUNK (KDIM / BK)            // 32
#define NSTAGE 3
#define NBLK   (NDIM / BN)            // 8
#define MAXTILES (MTOT / BM + NEXP)   // 136

#define ASTRIDE 128                   // A row bytes (8 x 16B segs, XOR swizzle)
#define BSTRIDE 144                   // B row bytes (128B data + 16B pad)
#define OFF_B   (128 * ASTRIDE)       // 16384
#define STAGE_BYTES (OFF_B + 128 * BSTRIDE)             // 34816
#define SMEM_TOTAL  (NSTAGE * STAGE_BYTES + 512 + 16)   // 104976

// epilogue compensation for two-sided tf32 truncation: 1 + 2 * 2^-11/(2 ln2)
#define OSCALE 1.000704f

// ---------------- device-global scratch ------------------------------------
__device__ int g_token_of_row[MTOT];
__device__ int g_tile_e[MAXTILES];
__device__ int g_tile_row0[MAXTILES];
__device__ int g_tile_rows[MAXTILES];
__device__ int g_njobs;
__device__ int g_job;

// ---------------- helpers ---------------------------------------------------
__device__ __forceinline__ uint32_t smem_to_u32(const void* p) {
    uint32_t a;
    asm("{ .reg .u64 t; cvta.to.shared.u64 t, %1; cvt.u32.u64 %0, t; }"
        : "=r"(a) : "l"(p));
    return a;
}

#define CPA16(dst_u32, src_ptr) \
    asm volatile("cp.async.cg.shared.global [%0], [%1], 16;" \
        :: "r"(dst_u32), "l"(src_ptr))
#define CPA_COMMIT() asm volatile("cp.async.commit_group;")
#define CPA_WAIT1()  asm volatile("cp.async.wait_group 1;")
#define CPA_WAIT0()  asm volatile("cp.async.wait_group 0;")

__device__ __forceinline__ void ldsm_x4(uint32_t r[4], uint32_t addr) {
    asm volatile("ldmatrix.sync.aligned.m8n8.x4.shared.b16 {%0,%1,%2,%3}, [%4];"
        : "=r"(r[0]), "=r"(r[1]), "=r"(r[2]), "=r"(r[3]) : "r"(addr));
}

__device__ __forceinline__ void mma_tf32(float d[4],
    const uint32_t a[4], uint32_t b0, uint32_t b1)
{
    asm volatile(
        "mma.sync.aligned.m16n8k8.row.col.f32.tf32.tf32.f32 "
        "{%0,%1,%2,%3}, {%4,%5,%6,%7}, {%8,%9}, {%0,%1,%2,%3};"
        : "+f"(d[0]), "+f"(d[1]), "+f"(d[2]), "+f"(d[3])
        : "r"(a[0]), "r"(a[1]), "r"(a[2]), "r"(a[3]), "r"(b0), "r"(b1));
}

// ---------------- tiny prep: token map + tile table only --------------------
#define MBLK (MTOT / 256)             // 64
#define PREP_GRID (MBLK + 1)

__global__ __launch_bounds__(256) void prep_all(
    const int* __restrict__ scatter, const int* __restrict__ splits)
{
    int b = blockIdx.x;
    if (b < MBLK) {
        int f = b * 256 + threadIdx.x;
        g_token_of_row[scatter[f]] = f / TOPK;
    } else if (threadIdx.x == 0) {
        int cum = 0, t = 0;
        for (int e = 0; e < NEXP; e++) {
            int cnt = splits[e];
            for (int r0 = 0; r0 < cnt; r0 += BM) {
                g_tile_e[t] = e;
                g_tile_row0[t] = cum + r0;
                g_tile_rows[t] = (cnt - r0 < BM) ? (cnt - r0) : BM;
                t++;
            }
            cum += cnt;
        }
        g_njobs = t * NBLK;
        g_job = 0;
    }
}

// ---------------- main GEMM --------------------------------------------------
// Stage: A 128 rows x 128B (seg^=(row&7)), gathered RAW from x;
//        B 128 rows x 128B data (144B stride) RAW from w.
__device__ __forceinline__ void load_stage(uint32_t sbuf, int c,
                                           const float* __restrict__ x,
                                           const float* __restrict__ w,
                                           int wbase, const int* s_tok, int tid)
{
    const size_t kb = (size_t)c * BK;
    #pragma unroll
    for (int i = 0; i < 8; i++) {
        int o = tid + i * 256;               // 0..2047
        const char* src;
        uint32_t dst;
        if (o < 1024) {                      // A (gathered raw fp32 x rows)
            int r   = o >> 3;
            int seg = o & 7;
            dst = sbuf + r * ASTRIDE + (uint32_t)((seg ^ (r & 7)) << 4);
            src = (const char*)(x + (size_t)s_tok[r] * KDIM + kb) + seg * 16;
        } else {                             // B (raw fp32 W rows)
            int o2  = o - 1024;
            int n   = o2 >> 3;
            int seg = ((o2 & 7) - (o2 >> 3)) & 7;   // write-conflict-free perm
            dst = sbuf + OFF_B + n * BSTRIDE + (uint32_t)(seg << 4);
            src = (const char*)(w + (size_t)(wbase + n) * KDIM + kb) + seg * 16;
        }
        CPA16(dst, src);
    }
}

__global__ __launch_bounds__(256, 2) void moe_gemm_tf32(
    const float* __restrict__ x, const float* __restrict__ w,
    float* __restrict__ out)
{
    extern __shared__ char smem_raw[];
    const uint32_t stage0 = smem_to_u32(smem_raw);
    int* s_tok = (int*)(smem_raw + NSTAGE * STAGE_BYTES);
    int* s_job = (int*)(smem_raw + NSTAGE * STAGE_BYTES + 512);

    const int tid  = threadIdx.x;
    const int wid  = tid >> 5;
    const int lane = tid & 31;
    const int wm   = wid & 3;          // 4 warps along M (32 rows each)
    const int wn   = wid >> 2;         // 2 warps along N (64 cols each)

    // ---- A fragment addressing (ldmatrix-b16-on-fp32) ----
    const int aq   = (lane >> 3) & 1;              // +8 rows for matrices 1,3
    const int skA  = lane >> 4;                    // +1 seg (k+4) for mats 2,3
    uint32_t baseA[2]; int maskA[2];
    #pragma unroll
    for (int mt = 0; mt < 2; mt++) {
        int r = wm * 32 + mt * 16 + aq * 8 + (lane & 7);
        baseA[mt] = (uint32_t)(r * ASTRIDE);
        maskA[mt] = r & 7;
    }
    // ---- B fragment addressing (ldmatrix-b16-on-fp32) ----
    const int bg   = lane >> 3;                    // matrix group 0..3
    const uint32_t baseB = (uint32_t)(
        (wn * 64 + ((bg >> 1) ? 8 : 0) + (lane & 7)) * BSTRIDE + (bg & 1) * 16);

    const int njobs = g_njobs;

    while (true) {
        __syncthreads();                          // smem free from previous job
        if (tid == 0) *s_job = atomicAdd(&g_job, 1);
        __syncthreads();
        const int job = *s_job;
        if (job >= njobs) break;

        const int tile = job >> 3;                // NBLK = 8
        const int nb   = job & 7;
        const int nrows = g_tile_rows[tile];
        const int row0  = g_tile_row0[tile];
        const int e     = g_tile_e[tile];
        const int n0    = nb * BN;
        const int wbase = e * NDIM + n0;

        if (tid < 128)
            s_tok[tid] = (tid < nrows) ? g_token_of_row[row0 + tid] : 0;
        __syncthreads();

        float acc[2][8][4];
        #pragma unroll
        for (int mt = 0; mt < 2; mt++)
            #pragma unroll
            for (int nt = 0; nt < 8; nt++)
                #pragma unroll
                for (int q = 0; q < 4; q++)
                    acc[mt][nt][q] = 0.0f;

        // prologue: 2 stages in flight
        load_stage(stage0, 0, x, w, wbase, s_tok, tid);
        CPA_COMMIT();
        load_stage(stage0 + STAGE_BYTES, 1, x, w, wbase, s_tok, tid);
        CPA_COMMIT();

        uint32_t sbuf = stage0;
        for (int c = 0; c < NCHUNK; c++) {
            if (c < NCHUNK - 1) { CPA_WAIT1(); } else { CPA_WAIT0(); }
            __syncthreads();                      // single barrier per chunk

            #pragma unroll
            for (int ks = 0; ks < 4; ks++) {
                // mid-chunk load placement (after 2 k-steps)
                if (ks == 2 && c + 2 < NCHUNK) {
                    uint32_t nbuf = sbuf + 2 * STAGE_BYTES;
                    if (nbuf >= stage0 + 3 * STAGE_BYTES) nbuf -= 3 * STAGE_BYTES;
                    load_stage(nbuf, c + 2, x, w, wbase, s_tok, tid);
                    CPA_COMMIT();
                }

                uint32_t Af[2][4];
                #pragma unroll
                for (int mt = 0; mt < 2; mt++) {
                    const uint32_t ao = baseA[mt] +
                        (uint32_t)(((ks * 2 + skA) ^ maskA[mt]) << 4);
                    ldsm_x4(Af[mt], sbuf + ao);   // raw fp32; HW truncates
                }
                const uint32_t bks = sbuf + OFF_B + baseB + (uint32_t)(ks * 32);
                #pragma unroll
                for (int j = 0; j < 4; j++) {
                    uint32_t Bf[4];               // b0,b1 of nt=2j; 2j+1
                    ldsm_x4(Bf, bks + (uint32_t)(j * 16 * BSTRIDE));
                    #pragma unroll
                    for (int mt = 0; mt < 2; mt++) {
                        mma_tf32(acc[mt][2 * j],     Af[mt], Bf[0], Bf[1]);
                        mma_tf32(acc[mt][2 * j + 1], Af[mt], Bf[2], Bf[3]);
                    }
                }
            }

            sbuf += STAGE_BYTES;
            if (sbuf >= stage0 + 3 * STAGE_BYTES) sbuf = stage0;
        }

        // epilogue: cancel two-sided truncation bias, then store
        const int g = lane >> 2;
        const int t = lane & 3;
        #pragma unroll
        for (int mt = 0; mt < 2; mt++) {
            const int mBase = wm * 32 + mt * 16;
            const int m0 = mBase + g;
            const int m1 = mBase + g + 8;
            float* r0p = out + (size_t)(row0 + m0) * NDIM + n0 + wn * 64 + 2 * t;
            float* r1p = out + (size_t)(row0 + m1) * NDIM + n0 + wn * 64 + 2 * t;
            #pragma unroll
            for (int nt = 0; nt < 8; nt++) {
                if (m0 < nrows) {
                    float2 v;
                    v.x = acc[mt][nt][0] * OSCALE;
                    v.y = acc[mt][nt][1] * OSCALE;
                    *(float2*)(r0p + nt * 8) = v;
                }
                if (m1 < nrows) {
                    float2 v;
                    v.x = acc[mt][nt][2] * OSCALE;
                    v.y = acc[mt][nt][3] * OSCALE;
                    *(float2*)(r1p + nt * 8) = v;
                }
            }
        }
    }
}

// ---------------------------------------------------------------------------
extern "C" void kernel_launch(void* const* d_in, const int* in_sizes, int n_in,
                              void* d_out, int out_size) {
    const float* x       = (const float*)d_in[0];
    const float* weights = (const float*)d_in[1];
    const int*   scatter = (const int*)d_in[2];
    const int*   splits  = (const int*)d_in[3];
    float*       out     = (float*)d_out;
    (void)in_sizes; (void)n_in; (void)out_size;

    cudaFuncSetAttribute(moe_gemm_tf32,
                         cudaFuncAttributeMaxDynamicSharedMemorySize, SMEM_TOTAL);

    prep_all<<<PREP_GRID, 256>>>(scatter, splits);
    moe_gemm_tf32<<<304, 256, SMEM_TOTAL>>>(x, weights, out);  // 2 CTAs/SM
}